// round 1
// baseline (speedup 1.0000x reference)
#include <cuda_runtime.h>
#include <cstdint>

#define NT 1000000
#define NC 500000
#define NM 100000
#define HID 16

// ---------------- scratch (static device globals; no allocation) ----------------
__device__ float g_ht[NT * HID];      // txn hidden state (in-place across layers)
__device__ float g_hc[NC * HID];      // card hidden state
__device__ float g_hm[NM * HID];      // merch hidden state
__device__ float g_bufc[NC * HID];    // Wh_c for current layer (gather source)
__device__ float g_bufm[NM * HID];    // Wh_m for current layer (gather source)
__device__ float g_sumc[NC * HID];    // segment sums for cards
__device__ float g_summ[NM * HID];    // segment sums for merchants
__device__ float g_cntc[NC];
__device__ float g_cntm[NM];

__device__ __forceinline__ float lrelu_f(float v) { return v > 0.f ? v : 0.01f * v; }

__device__ __forceinline__ void red4(float* p, float a, float b, float c, float d) {
    asm volatile("red.global.add.v4.f32 [%0], {%1,%2,%3,%4};"
                 :: "l"(p), "f"(a), "f"(b), "f"(c), "f"(d) : "memory");
}

// ---------------- zero sums + counts ----------------
__global__ void zero_kernel() {
    const int n1 = NC * HID;            // 8,000,000
    const int n2 = n1 + NM * HID;       // 9,600,000
    const int n3 = n2 + NC;             // 10,100,000
    const int n4 = n3 + NM;             // 10,200,000
    for (int i = blockIdx.x * blockDim.x + threadIdx.x; i < n4; i += gridDim.x * blockDim.x) {
        if (i < n1)      g_sumc[i] = 0.f;
        else if (i < n2) g_summ[i - n1] = 0.f;
        else if (i < n3) g_cntc[i - n2] = 0.f;
        else             g_cntm[i - n3] = 0.f;
    }
}

__global__ void count_kernel(const int* __restrict__ ci, const int* __restrict__ mi) {
    int i = blockIdx.x * blockDim.x + threadIdx.x;
    if (i < NT) {
        atomicAdd(&g_cntc[ci[i]], 1.f);
        atomicAdd(&g_cntm[mi[i]], 1.f);
    }
}

// ---------------- node projection: out[rows,16] = X[rows,K] @ W[K,16] + B ----------------
// 256 threads, TM=256 rows, per-thread tile 2 rows x 8 cols.
template <int K, bool LRELU>
__global__ __launch_bounds__(256) void kb_kernel(int nrows, const float* __restrict__ Xext,
                                                 int xsel,
                                                 const float* __restrict__ W,
                                                 const float* __restrict__ B,
                                                 int osel) {
    __shared__ float Xs[256 * 20];
    __shared__ float Ws[K * 16];

    const float* X = (xsel == 0) ? Xext : (xsel == 1 ? g_hc : g_hm);
    float* out = osel ? g_bufm : g_bufc;

    const int tid = threadIdx.x;
    const int cg = tid & 1;        // 2 col groups of 8
    const int rg = tid >> 1;       // 128 row groups; rows rg and rg+128
    const int row0 = blockIdx.x * 256;

    for (int i = tid; i < K * 16; i += 256) Ws[i] = W[i];

    float acc[2][8];
#pragma unroll
    for (int a = 0; a < 2; a++)
#pragma unroll
        for (int b = 0; b < 8; b++) acc[a][b] = 0.f;

    for (int ch = 0; ch < K / 16; ch++) {
        __syncthreads();
#pragma unroll
        for (int i = 0; i < 4; i++) {
            int idx = tid + i * 256;
            int r = idx >> 2, p = idx & 3;
            int row = row0 + r;
            float4 v = make_float4(0.f, 0.f, 0.f, 0.f);
            if (row < nrows) v = *(const float4*)(X + (size_t)row * K + ch * 16 + p * 4);
            if (LRELU) { v.x = lrelu_f(v.x); v.y = lrelu_f(v.y); v.z = lrelu_f(v.z); v.w = lrelu_f(v.w); }
            *(float4*)(Xs + r * 20 + p * 4) = v;
        }
        __syncthreads();
#pragma unroll
        for (int kk = 0; kk < 16; kk++) {
            const float* wr = &Ws[(ch * 16 + kk) * 16 + cg * 8];
            float4 w0 = *(const float4*)(wr);
            float4 w1 = *(const float4*)(wr + 4);
            float wv[8] = {w0.x, w0.y, w0.z, w0.w, w1.x, w1.y, w1.z, w1.w};
#pragma unroll
            for (int rr = 0; rr < 2; rr++) {
                float x = Xs[(rg + rr * 128) * 20 + kk];
#pragma unroll
                for (int cc = 0; cc < 8; cc++) acc[rr][cc] += x * wv[cc];
            }
        }
    }

    float4 bv0 = *(const float4*)(B + cg * 8);
    float4 bv1 = *(const float4*)(B + cg * 8 + 4);
#pragma unroll
    for (int rr = 0; rr < 2; rr++) {
        int row = row0 + rg + rr * 128;
        if (row < nrows) {
            float4 o0 = make_float4(acc[rr][0] + bv0.x, acc[rr][1] + bv0.y,
                                    acc[rr][2] + bv0.z, acc[rr][3] + bv0.w);
            float4 o1 = make_float4(acc[rr][4] + bv1.x, acc[rr][5] + bv1.y,
                                    acc[rr][6] + bv1.z, acc[rr][7] + bv1.w);
            *(float4*)(out + (size_t)row * 16 + cg * 8) = o0;
            *(float4*)(out + (size_t)row * 16 + cg * 8 + 4) = o1;
        }
    }
}

// ---------------- fused txn kernel: 3 projections [NT,48] + gather + scatter ----------------
// W points to a [3,K,16] contiguous block (etypes 2..4); B points to [3,16].
// cols 0..15 = Wh_s (self) -> h_t with gathers; 16..31 -> red into sumc; 32..47 -> red into summ.
// 256 threads, TM=256 rows, per-thread 4 rows x 12 cols.
template <int K, bool LRELU>
__global__ __launch_bounds__(256) void ka_kernel(const float* __restrict__ Xext, int use_ht,
                                                 const float* __restrict__ W,
                                                 const float* __restrict__ B,
                                                 const int* __restrict__ ci,
                                                 const int* __restrict__ mi) {
    __shared__ float Xs[256 * 20];
    __shared__ float Ws[K * 48];
    __shared__ float bs[48];
    __shared__ int ciS[256];
    __shared__ int miS[256];

    const float* X = use_ht ? g_ht : Xext;

    const int tid = threadIdx.x;
    const int cg = tid & 3;        // 4 col groups of 12
    const int rg = tid >> 2;       // 64 row groups; rows rg + rr*64
    const int row0 = blockIdx.x * 256;

    for (int i = tid; i < K * 48; i += 256) {
        int k = i / 48, c = i % 48;
        Ws[i] = W[(c >> 4) * (K * 16) + k * 16 + (c & 15)];
    }
    if (tid < 48) bs[tid] = B[tid];
    {
        int row = row0 + tid;
        ciS[tid] = (row < NT) ? ci[row] : 0;
        miS[tid] = (row < NT) ? mi[row] : 0;
    }

    float acc[4][12];
#pragma unroll
    for (int a = 0; a < 4; a++)
#pragma unroll
        for (int b = 0; b < 12; b++) acc[a][b] = 0.f;

    for (int ch = 0; ch < K / 16; ch++) {
        __syncthreads();
#pragma unroll
        for (int i = 0; i < 4; i++) {
            int idx = tid + i * 256;
            int r = idx >> 2, p = idx & 3;
            int row = row0 + r;
            float4 v = make_float4(0.f, 0.f, 0.f, 0.f);
            if (row < NT) v = *(const float4*)(X + (size_t)row * K + ch * 16 + p * 4);
            if (LRELU) { v.x = lrelu_f(v.x); v.y = lrelu_f(v.y); v.z = lrelu_f(v.z); v.w = lrelu_f(v.w); }
            *(float4*)(Xs + r * 20 + p * 4) = v;
        }
        __syncthreads();
#pragma unroll
        for (int kk = 0; kk < 16; kk++) {
            const float* wr = &Ws[(ch * 16 + kk) * 48 + cg * 12];
            float4 w0 = *(const float4*)(wr);
            float4 w1 = *(const float4*)(wr + 4);
            float4 w2 = *(const float4*)(wr + 8);
            float wv[12] = {w0.x, w0.y, w0.z, w0.w, w1.x, w1.y, w1.z, w1.w,
                            w2.x, w2.y, w2.z, w2.w};
#pragma unroll
            for (int rr = 0; rr < 4; rr++) {
                float x = Xs[(rg + rr * 64) * 20 + kk];
#pragma unroll
                for (int cc = 0; cc < 12; cc++) acc[rr][cc] += x * wv[cc];
            }
        }
    }

    const float4* bufc4 = (const float4*)g_bufc;
    const float4* bufm4 = (const float4*)g_bufm;
#pragma unroll
    for (int rr = 0; rr < 4; rr++) {
        int r = rg + rr * 64;
        int row = row0 + r;
        if (row < NT) {
            int cI = ciS[r], mI = miS[r];
#pragma unroll
            for (int u = 0; u < 3; u++) {
                int q = cg * 12 + u * 4;        // aligned quad, always within one etype block
                float vx = acc[rr][u * 4 + 0] + bs[q + 0];
                float vy = acc[rr][u * 4 + 1] + bs[q + 1];
                float vz = acc[rr][u * 4 + 2] + bs[q + 2];
                float vw = acc[rr][u * 4 + 3] + bs[q + 3];
                int e = q >> 4, j = q & 15;
                if (e == 0) {
                    float4 gc = bufc4[cI * 4 + (j >> 2)];
                    float4 gm = bufm4[mI * 4 + (j >> 2)];
                    float4 o = make_float4(vx + gc.x + gm.x, vy + gc.y + gm.y,
                                           vz + gc.z + gm.z, vw + gc.w + gm.w);
                    *(float4*)(g_ht + (size_t)row * 16 + j) = o;
                } else if (e == 1) {
                    red4(&g_sumc[(size_t)cI * 16 + j], vx, vy, vz, vw);
                } else {
                    red4(&g_summ[(size_t)mI * 16 + j], vx, vy, vz, vw);
                }
            }
        }
    }
}

// ---------------- segment mean finalize (+ re-zero sums for next layer) ----------------
__global__ void ke_kernel() {
    int i = blockIdx.x * blockDim.x + threadIdx.x;    // quad index
    const int q1 = NC * 4;
    const int qt = q1 + NM * 4;
    if (i >= qt) return;
    const float4 z = make_float4(0.f, 0.f, 0.f, 0.f);
    if (i < q1) {
        float inv = 1.f / fmaxf(g_cntc[i >> 2], 1.f);
        float4 v = ((float4*)g_sumc)[i];
        ((float4*)g_hc)[i] = make_float4(v.x * inv, v.y * inv, v.z * inv, v.w * inv);
        ((float4*)g_sumc)[i] = z;
    } else {
        int j = i - q1;
        float inv = 1.f / fmaxf(g_cntm[j >> 2], 1.f);
        float4 v = ((float4*)g_summ)[j];
        ((float4*)g_hm)[j] = make_float4(v.x * inv, v.y * inv, v.z * inv, v.w * inv);
        ((float4*)g_summ)[j] = z;
    }
}

// ---------------- final txn kernel: layer-2 h_t fused with @W_out + b_out ----------------
// 256 threads, TM=256, per-thread 2 rows x 8 cols; pair-reduce across the 2 col groups.
__global__ __launch_bounds__(256) void ka_out_kernel(const float* __restrict__ W,
                                                     const float* __restrict__ B,
                                                     const int* __restrict__ ci,
                                                     const int* __restrict__ mi,
                                                     const float* __restrict__ Wout,
                                                     const float* __restrict__ Bout,
                                                     float* __restrict__ out) {
    __shared__ float Xs[256 * 20];
    __shared__ float Ws[16 * 16];
    __shared__ float bs[16];
    __shared__ float wo[32];
    __shared__ int ciS[256];
    __shared__ int miS[256];

    const int tid = threadIdx.x;
    const int cg = tid & 1;
    const int rg = tid >> 1;
    const int row0 = blockIdx.x * 256;

    if (tid < 256) Ws[tid] = W[tid];
    if (tid < 16) bs[tid] = B[tid];
    if (tid < 32) wo[tid] = Wout[tid];
    {
        int row = row0 + tid;
        ciS[tid] = (row < NT) ? ci[row] : 0;
        miS[tid] = (row < NT) ? mi[row] : 0;
    }
#pragma unroll
    for (int i = 0; i < 4; i++) {
        int idx = tid + i * 256;
        int r = idx >> 2, p = idx & 3;
        int row = row0 + r;
        float4 v = make_float4(0.f, 0.f, 0.f, 0.f);
        if (row < NT) v = *(const float4*)(g_ht + (size_t)row * 16 + p * 4);
        v.x = lrelu_f(v.x); v.y = lrelu_f(v.y); v.z = lrelu_f(v.z); v.w = lrelu_f(v.w);
        *(float4*)(Xs + r * 20 + p * 4) = v;
    }
    __syncthreads();

    float acc[2][8];
#pragma unroll
    for (int a = 0; a < 2; a++)
#pragma unroll
        for (int b = 0; b < 8; b++) acc[a][b] = 0.f;

#pragma unroll
    for (int kk = 0; kk < 16; kk++) {
        const float* wr = &Ws[kk * 16 + cg * 8];
        float4 w0 = *(const float4*)(wr);
        float4 w1 = *(const float4*)(wr + 4);
        float wv[8] = {w0.x, w0.y, w0.z, w0.w, w1.x, w1.y, w1.z, w1.w};
#pragma unroll
        for (int rr = 0; rr < 2; rr++) {
            float x = Xs[(rg + rr * 128) * 20 + kk];
#pragma unroll
            for (int cc = 0; cc < 8; cc++) acc[rr][cc] += x * wv[cc];
        }
    }

    const float4* bufc4 = (const float4*)g_bufc;
    const float4* bufm4 = (const float4*)g_bufm;
    float b0o = Bout[0], b1o = Bout[1];

#pragma unroll
    for (int rr = 0; rr < 2; rr++) {
        int r = rg + rr * 128;
        int row = row0 + r;
        int cI = ciS[r], mI = miS[r];
        float o0 = 0.f, o1 = 0.f;
#pragma unroll
        for (int u = 0; u < 2; u++) {
            int q = cg * 8 + u * 4;
            float4 gc = bufc4[cI * 4 + (q >> 2)];
            float4 gm = bufm4[mI * 4 + (q >> 2)];
            float vx = acc[rr][u * 4 + 0] + bs[q + 0] + gc.x + gm.x;
            float vy = acc[rr][u * 4 + 1] + bs[q + 1] + gc.y + gm.y;
            float vz = acc[rr][u * 4 + 2] + bs[q + 2] + gc.z + gm.z;
            float vw = acc[rr][u * 4 + 3] + bs[q + 3] + gc.w + gm.w;
            o0 += vx * wo[(q + 0) * 2 + 0] + vy * wo[(q + 1) * 2 + 0]
                + vz * wo[(q + 2) * 2 + 0] + vw * wo[(q + 3) * 2 + 0];
            o1 += vx * wo[(q + 0) * 2 + 1] + vy * wo[(q + 1) * 2 + 1]
                + vz * wo[(q + 2) * 2 + 1] + vw * wo[(q + 3) * 2 + 1];
        }
        // partner lane tid^1 has same row (same rg), other 8 columns
        o0 += __shfl_xor_sync(0xffffffffu, o0, 1);
        o1 += __shfl_xor_sync(0xffffffffu, o1, 1);
        if (cg == 0 && row < NT) {
            out[(size_t)row * 2 + 0] = o0 + b0o;
            out[(size_t)row * 2 + 1] = o1 + b1o;
        }
    }
}

// ---------------- launcher ----------------
extern "C" void kernel_launch(void* const* d_in, const int* in_sizes, int n_in,
                              void* d_out, int out_size) {
    (void)in_sizes; (void)n_in; (void)out_size;
    const float* feats     = (const float*)d_in[0];
    const float* emb_card  = (const float*)d_in[1];
    const float* emb_merch = (const float*)d_in[2];
    const float* W0        = (const float*)d_in[3];
    const float* b0        = (const float*)d_in[4];
    const float* W1        = (const float*)d_in[5];
    const float* b1        = (const float*)d_in[6];
    const float* W2        = (const float*)d_in[7];
    const float* b2        = (const float*)d_in[8];
    const float* Wout      = (const float*)d_in[9];
    const float* bout      = (const float*)d_in[10];
    const int*   ci        = (const int*)d_in[11];
    const int*   mi        = (const int*)d_in[12];
    float* out = (float*)d_out;

    const int GB_T = (NT + 255) / 256;   // 3907
    const int GB_C = (NC + 255) / 256;   // 1954
    const int GB_M = (NM + 255) / 256;   // 391
    const int GB_E = ((NC + NM) * 4 + 255) / 256;  // 9375

    zero_kernel<<<4096, 256>>>();
    count_kernel<<<GB_T, 256>>>(ci, mi);

    // Layer 0 (K=128): W0 is [5,128,16] -> etype stride 2048; b0 stride 16
    kb_kernel<128, false><<<GB_C, 256>>>(NC, emb_card,  0, W0,        b0,      0);
    kb_kernel<128, false><<<GB_M, 256>>>(NM, emb_merch, 0, W0 + 2048, b0 + 16, 1);
    ka_kernel<128, false><<<GB_T, 256>>>(feats, 0, W0 + 4096, b0 + 32, ci, mi);
    ke_kernel<<<GB_E, 256>>>();

    // Layer 1 (K=16): W1 is [5,16,16] -> etype stride 256
    kb_kernel<16, true><<<GB_C, 256>>>(NC, nullptr, 1, W1,       b1,      0);
    kb_kernel<16, true><<<GB_M, 256>>>(NM, nullptr, 2, W1 + 256, b1 + 16, 1);
    ka_kernel<16, true><<<GB_T, 256>>>(nullptr, 1, W1 + 512, b1 + 32, ci, mi);
    ke_kernel<<<GB_E, 256>>>();

    // Layer 2: only need bufc/bufm + self projection, fused with output head
    kb_kernel<16, true><<<GB_C, 256>>>(NC, nullptr, 1, W2,       b2,      0);
    kb_kernel<16, true><<<GB_M, 256>>>(NM, nullptr, 2, W2 + 256, b2 + 16, 1);
    ka_out_kernel<<<GB_T, 256>>>(W2 + 512, b2 + 32, ci, mi, Wout, bout, out);
}

// round 3
// speedup vs baseline: 1.3270x; 1.3270x over previous
#include <cuda_runtime.h>
#include <cstdint>

#define NT 1000000
#define NC 500000
#define NM 100000
#define HID 16

// ---------------- scratch (static device globals; no allocation) ----------------
__device__ float g_ht[NT * HID];      // txn hidden state (in-place across layers)
__device__ float g_hc[NC * HID];      // card hidden state
__device__ float g_hm[NM * HID];      // merch hidden state
__device__ float g_bufc[NC * HID];    // Wh_c for current layer (gather source)
__device__ float g_bufm[NM * HID];    // Wh_m for current layer (gather source)
__device__ float g_sumc[NC * HID];    // segment sums for cards
__device__ float g_summ[NM * HID];    // segment sums for merchants
__device__ float g_cntc[NC];
__device__ float g_cntm[NM];

__device__ __forceinline__ float lrelu_f(float v) { return v > 0.f ? v : 0.01f * v; }

__device__ __forceinline__ void red4(float* p, float a, float b, float c, float d) {
    asm volatile("red.global.add.v4.f32 [%0], {%1,%2,%3,%4};"
                 :: "l"(p), "f"(a), "f"(b), "f"(c), "f"(d) : "memory");
}

__device__ __forceinline__ uint32_t f2tf32(float f) {
    uint32_t r; asm("cvt.rna.tf32.f32 %0, %1;" : "=r"(r) : "f"(f)); return r;
}

__device__ __forceinline__ void mma_tf32(float& d0, float& d1, float& d2, float& d3,
                                         uint32_t a0, uint32_t a1, uint32_t a2, uint32_t a3,
                                         uint32_t b0, uint32_t b1) {
    asm volatile("mma.sync.aligned.m16n8k8.row.col.f32.tf32.tf32.f32 "
                 "{%0,%1,%2,%3}, {%4,%5,%6,%7}, {%8,%9}, {%0,%1,%2,%3};"
                 : "+f"(d0), "+f"(d1), "+f"(d2), "+f"(d3)
                 : "r"(a0), "r"(a1), "r"(a2), "r"(a3), "r"(b0), "r"(b1));
}

__device__ __forceinline__ void cp_async16(void* dst_smem, const void* src, bool pred) {
    uint32_t d = (uint32_t)__cvta_generic_to_shared(dst_smem);
    asm volatile("cp.async.cg.shared.global [%0], [%1], 16, %2;"
                 :: "r"(d), "l"(src), "r"(pred ? 16 : 0));
}
#define CP_COMMIT() asm volatile("cp.async.commit_group;")
#define CP_WAIT1()  asm volatile("cp.async.wait_group 1;")

// ---------------- zero sums + counts ----------------
__global__ void zero_kernel() {
    const int n1 = NC * HID;
    const int n2 = n1 + NM * HID;
    const int n3 = n2 + NC;
    const int n4 = n3 + NM;
    for (int i = blockIdx.x * blockDim.x + threadIdx.x; i < n4; i += gridDim.x * blockDim.x) {
        if (i < n1)      g_sumc[i] = 0.f;
        else if (i < n2) g_summ[i - n1] = 0.f;
        else if (i < n3) g_cntc[i - n2] = 0.f;
        else             g_cntm[i - n3] = 0.f;
    }
}

__global__ void count_kernel(const int* __restrict__ ci, const int* __restrict__ mi) {
    int i = blockIdx.x * blockDim.x + threadIdx.x;
    if (i < NT) {
        atomicAdd(&g_cntc[ci[i]], 1.f);
        atomicAdd(&g_cntm[mi[i]], 1.f);
    }
}

// ================= Layer-0 node projection via TF32 MMA =================
// out[rows,16] = X[rows,128] @ W[128,16] + B.  Block = 128 rows, 8 warps,
// each warp: 16 rows x 16 cols (2 n-tiles).  3-stage cp.async pipeline.
__global__ __launch_bounds__(256) void kb0_mma(int nrows, const float* __restrict__ X,
                                               const float* __restrict__ W,
                                               const float* __restrict__ B,
                                               int osel) {
    __shared__ __align__(16) float Xs[3][128][20];
    __shared__ __align__(16) uint32_t Ws[128][24];   // stride 24: conflict-free B reads
    __shared__ float bs[16];

    float* out = osel ? g_bufm : g_bufc;
    const int tid = threadIdx.x;
    const int lane = tid & 31, wid = tid >> 5;
    const int gid = lane >> 2, tig = lane & 3;
    const int row0 = blockIdx.x * 128;

    for (int i = tid; i < 128 * 16; i += 256) Ws[i >> 4][i & 15] = f2tf32(W[i]);
    if (tid < 16) bs[tid] = B[tid];

    float c[2][4];
#pragma unroll
    for (int a = 0; a < 2; a++)
#pragma unroll
        for (int b = 0; b < 4; b++) c[a][b] = 0.f;

    auto prefetch = [&](int ch, int st) {
#pragma unroll
        for (int j = 0; j < 2; j++) {
            int idx = tid + j * 256;
            int r = idx >> 2, p = idx & 3;
            int row = row0 + r;
            bool ok = row < nrows;
            const float* src = X + (size_t)(ok ? row : 0) * 128 + ch * 16 + p * 4;
            cp_async16(&Xs[st][r][p * 4], src, ok);
        }
    };

    prefetch(0, 0); CP_COMMIT();
    prefetch(1, 1); CP_COMMIT();

    for (int ch = 0; ch < 8; ch++) {
        CP_WAIT1();
        __syncthreads();
        if (ch + 2 < 8) prefetch(ch + 2, (ch + 2) % 3);
        CP_COMMIT();
        const float(*xb)[20] = Xs[ch % 3];
#pragma unroll
        for (int ks = 0; ks < 2; ks++) {
            int k0 = ks * 8;
            uint32_t a0 = f2tf32(xb[wid * 16 + gid][k0 + tig]);
            uint32_t a1 = f2tf32(xb[wid * 16 + 8 + gid][k0 + tig]);
            uint32_t a2 = f2tf32(xb[wid * 16 + gid][k0 + tig + 4]);
            uint32_t a3 = f2tf32(xb[wid * 16 + 8 + gid][k0 + tig + 4]);
            int kk = ch * 16 + k0;
#pragma unroll
            for (int nt = 0; nt < 2; nt++) {
                uint32_t b0 = Ws[kk + tig][nt * 8 + gid];
                uint32_t b1 = Ws[kk + tig + 4][nt * 8 + gid];
                mma_tf32(c[nt][0], c[nt][1], c[nt][2], c[nt][3], a0, a1, a2, a3, b0, b1);
            }
        }
    }

    // epilogue: direct global stores (float2), bias added
#pragma unroll
    for (int nt = 0; nt < 2; nt++) {
        int col = nt * 8 + 2 * tig;
        int r0_ = row0 + wid * 16 + gid;
        int r1_ = r0_ + 8;
        if (r0_ < nrows)
            *(float2*)(out + (size_t)r0_ * 16 + col) =
                make_float2(c[nt][0] + bs[col], c[nt][1] + bs[col + 1]);
        if (r1_ < nrows)
            *(float2*)(out + (size_t)r1_ * 16 + col) =
                make_float2(c[nt][2] + bs[col], c[nt][3] + bs[col + 1]);
    }
}

// ================= Layer-0 fused txn kernel via TF32 MMA =================
// 3 projections [128 rows x 48 cols], K=128; then gather + scatter epilogue.
// Dynamic smem layout:
//   [0, 30720)           float Xs[3][128][20]
//   [30720, 59392)       uint32_t Ws[128][56]  (48 used; stride 56 = conflict-free)
//                        reused after mainloop as float Cs[128][48]
//   [59392, 59584)       float bs[48]
//   [59584, 60096)       int ciS[128]
//   [60096, 60608)       int miS[128]
static const int KA0_SMEM = 60608;

__global__ __launch_bounds__(256) void ka0_mma(const float* __restrict__ X,
                                               const float* __restrict__ W,
                                               const float* __restrict__ B,
                                               const int* __restrict__ ci,
                                               const int* __restrict__ mi) {
    extern __shared__ __align__(16) char smem_raw[];
    float(*Xs)[128][20] = (float(*)[128][20])smem_raw;
    uint32_t(*Ws)[56] = (uint32_t(*)[56])(smem_raw + 30720);
    float* Cs = (float*)(smem_raw + 30720);
    float* bs = (float*)(smem_raw + 59392);
    int* ciS = (int*)(smem_raw + 59584);
    int* miS = (int*)(smem_raw + 60096);

    const int tid = threadIdx.x;
    const int lane = tid & 31, wid = tid >> 5;
    const int gid = lane >> 2, tig = lane & 3;
    const int row0 = blockIdx.x * 128;

    // W -> Ws (tf32), layout [k][c] with c in 0..47 spanning etypes 2..4
    for (int i = tid; i < 128 * 48; i += 256) {
        int k = i / 48, cc = i % 48;
        Ws[k][cc] = f2tf32(W[(cc >> 4) * 2048 + k * 16 + (cc & 15)]);
    }
    if (tid < 48) bs[tid] = B[tid];
    if (tid < 128) {
        int row = row0 + tid;
        ciS[tid] = (row < NT) ? ci[row] : 0;
        miS[tid] = (row < NT) ? mi[row] : 0;
    }

    float c[6][4];
#pragma unroll
    for (int a = 0; a < 6; a++)
#pragma unroll
        for (int b = 0; b < 4; b++) c[a][b] = 0.f;

    auto prefetch = [&](int ch, int st) {
#pragma unroll
        for (int j = 0; j < 2; j++) {
            int idx = tid + j * 256;
            int r = idx >> 2, p = idx & 3;
            int row = row0 + r;
            bool ok = row < NT;
            const float* src = X + (size_t)(ok ? row : 0) * 128 + ch * 16 + p * 4;
            cp_async16(&Xs[st][r][p * 4], src, ok);
        }
    };

    prefetch(0, 0); CP_COMMIT();
    prefetch(1, 1); CP_COMMIT();

    for (int ch = 0; ch < 8; ch++) {
        CP_WAIT1();
        __syncthreads();
        if (ch + 2 < 8) prefetch(ch + 2, (ch + 2) % 3);
        CP_COMMIT();
        const float(*xb)[20] = Xs[ch % 3];
#pragma unroll
        for (int ks = 0; ks < 2; ks++) {
            int k0 = ks * 8;
            uint32_t a0 = f2tf32(xb[wid * 16 + gid][k0 + tig]);
            uint32_t a1 = f2tf32(xb[wid * 16 + 8 + gid][k0 + tig]);
            uint32_t a2 = f2tf32(xb[wid * 16 + gid][k0 + tig + 4]);
            uint32_t a3 = f2tf32(xb[wid * 16 + 8 + gid][k0 + tig + 4]);
            int kk = ch * 16 + k0;
#pragma unroll
            for (int nt = 0; nt < 6; nt++) {
                uint32_t b0 = Ws[kk + tig][nt * 8 + gid];
                uint32_t b1 = Ws[kk + tig + 4][nt * 8 + gid];
                mma_tf32(c[nt][0], c[nt][1], c[nt][2], c[nt][3], a0, a1, a2, a3, b0, b1);
            }
        }
    }

    // dump C frags to smem (Ws region is dead now)
    __syncthreads();
#pragma unroll
    for (int nt = 0; nt < 6; nt++) {
        int col = nt * 8 + 2 * tig;
        int ra = wid * 16 + gid, rb = ra + 8;
        *(float2*)(Cs + ra * 48 + col) = make_float2(c[nt][0], c[nt][1]);
        *(float2*)(Cs + rb * 48 + col) = make_float2(c[nt][2], c[nt][3]);
    }
    __syncthreads();

    // epilogue: 4 threads per row, 2 passes of 64 rows
    const float4* bufc4 = (const float4*)g_bufc;
    const float4* bufm4 = (const float4*)g_bufm;
    const int cg = tid & 3;
    const int rg = tid >> 2;
#pragma unroll
    for (int pass = 0; pass < 2; pass++) {
        int r = pass * 64 + rg;
        int row = row0 + r;
        if (row < NT) {
            int cI = ciS[r], mI = miS[r];
#pragma unroll
            for (int u = 0; u < 3; u++) {
                int q = cg * 12 + u * 4;
                float4 v = *(const float4*)(Cs + r * 48 + q);
                float vx = v.x + bs[q + 0];
                float vy = v.y + bs[q + 1];
                float vz = v.z + bs[q + 2];
                float vw = v.w + bs[q + 3];
                int e = q >> 4, j = q & 15;
                if (e == 0) {
                    float4 gc = bufc4[cI * 4 + (j >> 2)];
                    float4 gm = bufm4[mI * 4 + (j >> 2)];
                    float4 o = make_float4(vx + gc.x + gm.x, vy + gc.y + gm.y,
                                           vz + gc.z + gm.z, vw + gc.w + gm.w);
                    *(float4*)(g_ht + (size_t)row * 16 + j) = o;
                } else if (e == 1) {
                    red4(&g_sumc[(size_t)cI * 16 + j], vx, vy, vz, vw);
                } else {
                    red4(&g_summ[(size_t)mI * 16 + j], vx, vy, vz, vw);
                }
            }
        }
    }
}

// ---------------- node projection (K=16, FFMA path, layers 1-2) ----------------
template <int K, bool LRELU>
__global__ __launch_bounds__(256) void kb_kernel(int nrows, const float* __restrict__ Xext,
                                                 int xsel,
                                                 const float* __restrict__ W,
                                                 const float* __restrict__ B,
                                                 int osel) {
    __shared__ float Xs[256 * 20];
    __shared__ float Ws[K * 16];

    const float* X = (xsel == 0) ? Xext : (xsel == 1 ? g_hc : g_hm);
    float* out = osel ? g_bufm : g_bufc;

    const int tid = threadIdx.x;
    const int cg = tid & 1;
    const int rg = tid >> 1;
    const int row0 = blockIdx.x * 256;

    for (int i = tid; i < K * 16; i += 256) Ws[i] = W[i];

    float acc[2][8];
#pragma unroll
    for (int a = 0; a < 2; a++)
#pragma unroll
        for (int b = 0; b < 8; b++) acc[a][b] = 0.f;

    for (int ch = 0; ch < K / 16; ch++) {
        __syncthreads();
#pragma unroll
        for (int i = 0; i < 4; i++) {
            int idx = tid + i * 256;
            int r = idx >> 2, p = idx & 3;
            int row = row0 + r;
            float4 v = make_float4(0.f, 0.f, 0.f, 0.f);
            if (row < nrows) v = *(const float4*)(X + (size_t)row * K + ch * 16 + p * 4);
            if (LRELU) { v.x = lrelu_f(v.x); v.y = lrelu_f(v.y); v.z = lrelu_f(v.z); v.w = lrelu_f(v.w); }
            *(float4*)(Xs + r * 20 + p * 4) = v;
        }
        __syncthreads();
#pragma unroll
        for (int kk = 0; kk < 16; kk++) {
            const float* wr = &Ws[(ch * 16 + kk) * 16 + cg * 8];
            float4 w0 = *(const float4*)(wr);
            float4 w1 = *(const float4*)(wr + 4);
            float wv[8] = {w0.x, w0.y, w0.z, w0.w, w1.x, w1.y, w1.z, w1.w};
#pragma unroll
            for (int rr = 0; rr < 2; rr++) {
                float x = Xs[(rg + rr * 128) * 20 + kk];
#pragma unroll
                for (int cc = 0; cc < 8; cc++) acc[rr][cc] += x * wv[cc];
            }
        }
    }

    float4 bv0 = *(const float4*)(B + cg * 8);
    float4 bv1 = *(const float4*)(B + cg * 8 + 4);
#pragma unroll
    for (int rr = 0; rr < 2; rr++) {
        int row = row0 + rg + rr * 128;
        if (row < nrows) {
            float4 o0 = make_float4(acc[rr][0] + bv0.x, acc[rr][1] + bv0.y,
                                    acc[rr][2] + bv0.z, acc[rr][3] + bv0.w);
            float4 o1 = make_float4(acc[rr][4] + bv1.x, acc[rr][5] + bv1.y,
                                    acc[rr][6] + bv1.z, acc[rr][7] + bv1.w);
            *(float4*)(out + (size_t)row * 16 + cg * 8) = o0;
            *(float4*)(out + (size_t)row * 16 + cg * 8 + 4) = o1;
        }
    }
}

// ---------------- fused txn kernel (K=16, FFMA path, layer 1) ----------------
template <int K, bool LRELU>
__global__ __launch_bounds__(256) void ka_kernel(const float* __restrict__ Xext, int use_ht,
                                                 const float* __restrict__ W,
                                                 const float* __restrict__ B,
                                                 const int* __restrict__ ci,
                                                 const int* __restrict__ mi) {
    __shared__ float Xs[256 * 20];
    __shared__ float Ws[K * 48];
    __shared__ float bs[48];
    __shared__ int ciS[256];
    __shared__ int miS[256];

    const float* X = use_ht ? g_ht : Xext;

    const int tid = threadIdx.x;
    const int cg = tid & 3;
    const int rg = tid >> 2;
    const int row0 = blockIdx.x * 256;

    for (int i = tid; i < K * 48; i += 256) {
        int k = i / 48, c = i % 48;
        Ws[i] = W[(c >> 4) * (K * 16) + k * 16 + (c & 15)];
    }
    if (tid < 48) bs[tid] = B[tid];
    {
        int row = row0 + tid;
        ciS[tid] = (row < NT) ? ci[row] : 0;
        miS[tid] = (row < NT) ? mi[row] : 0;
    }

    float acc[4][12];
#pragma unroll
    for (int a = 0; a < 4; a++)
#pragma unroll
        for (int b = 0; b < 12; b++) acc[a][b] = 0.f;

    for (int ch = 0; ch < K / 16; ch++) {
        __syncthreads();
#pragma unroll
        for (int i = 0; i < 4; i++) {
            int idx = tid + i * 256;
            int r = idx >> 2, p = idx & 3;
            int row = row0 + r;
            float4 v = make_float4(0.f, 0.f, 0.f, 0.f);
            if (row < NT) v = *(const float4*)(X + (size_t)row * K + ch * 16 + p * 4);
            if (LRELU) { v.x = lrelu_f(v.x); v.y = lrelu_f(v.y); v.z = lrelu_f(v.z); v.w = lrelu_f(v.w); }
            *(float4*)(Xs + r * 20 + p * 4) = v;
        }
        __syncthreads();
#pragma unroll
        for (int kk = 0; kk < 16; kk++) {
            const float* wr = &Ws[(ch * 16 + kk) * 48 + cg * 12];
            float4 w0 = *(const float4*)(wr);
            float4 w1 = *(const float4*)(wr + 4);
            float4 w2 = *(const float4*)(wr + 8);
            float wv[12] = {w0.x, w0.y, w0.z, w0.w, w1.x, w1.y, w1.z, w1.w,
                            w2.x, w2.y, w2.z, w2.w};
#pragma unroll
            for (int rr = 0; rr < 4; rr++) {
                float x = Xs[(rg + rr * 64) * 20 + kk];
#pragma unroll
                for (int cc = 0; cc < 12; cc++) acc[rr][cc] += x * wv[cc];
            }
        }
    }

    const float4* bufc4 = (const float4*)g_bufc;
    const float4* bufm4 = (const float4*)g_bufm;
#pragma unroll
    for (int rr = 0; rr < 4; rr++) {
        int r = rg + rr * 64;
        int row = row0 + r;
        if (row < NT) {
            int cI = ciS[r], mI = miS[r];
#pragma unroll
            for (int u = 0; u < 3; u++) {
                int q = cg * 12 + u * 4;
                float vx = acc[rr][u * 4 + 0] + bs[q + 0];
                float vy = acc[rr][u * 4 + 1] + bs[q + 1];
                float vz = acc[rr][u * 4 + 2] + bs[q + 2];
                float vw = acc[rr][u * 4 + 3] + bs[q + 3];
                int e = q >> 4, j = q & 15;
                if (e == 0) {
                    float4 gc = bufc4[cI * 4 + (j >> 2)];
                    float4 gm = bufm4[mI * 4 + (j >> 2)];
                    float4 o = make_float4(vx + gc.x + gm.x, vy + gc.y + gm.y,
                                           vz + gc.z + gm.z, vw + gc.w + gm.w);
                    *(float4*)(g_ht + (size_t)row * 16 + j) = o;
                } else if (e == 1) {
                    red4(&g_sumc[(size_t)cI * 16 + j], vx, vy, vz, vw);
                } else {
                    red4(&g_summ[(size_t)mI * 16 + j], vx, vy, vz, vw);
                }
            }
        }
    }
}

// ---------------- segment mean finalize (+ re-zero sums for next layer) ----------------
__global__ void ke_kernel() {
    int i = blockIdx.x * blockDim.x + threadIdx.x;
    const int q1 = NC * 4;
    const int qt = q1 + NM * 4;
    if (i >= qt) return;
    const float4 z = make_float4(0.f, 0.f, 0.f, 0.f);
    if (i < q1) {
        float inv = 1.f / fmaxf(g_cntc[i >> 2], 1.f);
        float4 v = ((float4*)g_sumc)[i];
        ((float4*)g_hc)[i] = make_float4(v.x * inv, v.y * inv, v.z * inv, v.w * inv);
        ((float4*)g_sumc)[i] = z;
    } else {
        int j = i - q1;
        float inv = 1.f / fmaxf(g_cntm[j >> 2], 1.f);
        float4 v = ((float4*)g_summ)[j];
        ((float4*)g_hm)[j] = make_float4(v.x * inv, v.y * inv, v.z * inv, v.w * inv);
        ((float4*)g_summ)[j] = z;
    }
}

// ---------------- final txn kernel: layer-2 h_t fused with @W_out + b_out ----------------
__global__ __launch_bounds__(256) void ka_out_kernel(const float* __restrict__ W,
                                                     const float* __restrict__ B,
                                                     const int* __restrict__ ci,
                                                     const int* __restrict__ mi,
                                                     const float* __restrict__ Wout,
                                                     const float* __restrict__ Bout,
                                                     float* __restrict__ out) {
    __shared__ float Xs[256 * 20];
    __shared__ float Ws[16 * 16];
    __shared__ float bs[16];
    __shared__ float wo[32];
    __shared__ int ciS[256];
    __shared__ int miS[256];

    const int tid = threadIdx.x;
    const int cg = tid & 1;
    const int rg = tid >> 1;
    const int row0 = blockIdx.x * 256;

    if (tid < 256) Ws[tid] = W[tid];
    if (tid < 16) bs[tid] = B[tid];
    if (tid < 32) wo[tid] = Wout[tid];
    {
        int row = row0 + tid;
        ciS[tid] = (row < NT) ? ci[row] : 0;
        miS[tid] = (row < NT) ? mi[row] : 0;
    }
#pragma unroll
    for (int i = 0; i < 4; i++) {
        int idx = tid + i * 256;
        int r = idx >> 2, p = idx & 3;
        int row = row0 + r;
        float4 v = make_float4(0.f, 0.f, 0.f, 0.f);
        if (row < NT) v = *(const float4*)(g_ht + (size_t)row * 16 + p * 4);
        v.x = lrelu_f(v.x); v.y = lrelu_f(v.y); v.z = lrelu_f(v.z); v.w = lrelu_f(v.w);
        *(float4*)(Xs + r * 20 + p * 4) = v;
    }
    __syncthreads();

    float acc[2][8];
#pragma unroll
    for (int a = 0; a < 2; a++)
#pragma unroll
        for (int b = 0; b < 8; b++) acc[a][b] = 0.f;

#pragma unroll
    for (int kk = 0; kk < 16; kk++) {
        const float* wr = &Ws[kk * 16 + cg * 8];
        float4 w0 = *(const float4*)(wr);
        float4 w1 = *(const float4*)(wr + 4);
        float wv[8] = {w0.x, w0.y, w0.z, w0.w, w1.x, w1.y, w1.z, w1.w};
#pragma unroll
        for (int rr = 0; rr < 2; rr++) {
            float x = Xs[(rg + rr * 128) * 20 + kk];
#pragma unroll
            for (int cc = 0; cc < 8; cc++) acc[rr][cc] += x * wv[cc];
        }
    }

    const float4* bufc4 = (const float4*)g_bufc;
    const float4* bufm4 = (const float4*)g_bufm;
    float b0o = Bout[0], b1o = Bout[1];

#pragma unroll
    for (int rr = 0; rr < 2; rr++) {
        int r = rg + rr * 128;
        int row = row0 + r;
        int cI = ciS[r], mI = miS[r];
        float o0 = 0.f, o1 = 0.f;
#pragma unroll
        for (int u = 0; u < 2; u++) {
            int q = cg * 8 + u * 4;
            float4 gc = bufc4[cI * 4 + (q >> 2)];
            float4 gm = bufm4[mI * 4 + (q >> 2)];
            float vx = acc[rr][u * 4 + 0] + bs[q + 0] + gc.x + gm.x;
            float vy = acc[rr][u * 4 + 1] + bs[q + 1] + gc.y + gm.y;
            float vz = acc[rr][u * 4 + 2] + bs[q + 2] + gc.z + gm.z;
            float vw = acc[rr][u * 4 + 3] + bs[q + 3] + gc.w + gm.w;
            o0 += vx * wo[(q + 0) * 2 + 0] + vy * wo[(q + 1) * 2 + 0]
                + vz * wo[(q + 2) * 2 + 0] + vw * wo[(q + 3) * 2 + 0];
            o1 += vx * wo[(q + 0) * 2 + 1] + vy * wo[(q + 1) * 2 + 1]
                + vz * wo[(q + 2) * 2 + 1] + vw * wo[(q + 3) * 2 + 1];
        }
        o0 += __shfl_xor_sync(0xffffffffu, o0, 1);
        o1 += __shfl_xor_sync(0xffffffffu, o1, 1);
        if (cg == 0 && row < NT) {
            out[(size_t)row * 2 + 0] = o0 + b0o;
            out[(size_t)row * 2 + 1] = o1 + b1o;
        }
    }
}

// ---------------- launcher ----------------
extern "C" void kernel_launch(void* const* d_in, const int* in_sizes, int n_in,
                              void* d_out, int out_size) {
    (void)in_sizes; (void)n_in; (void)out_size;
    const float* feats     = (const float*)d_in[0];
    const float* emb_card  = (const float*)d_in[1];
    const float* emb_merch = (const float*)d_in[2];
    const float* W0        = (const float*)d_in[3];
    const float* b0        = (const float*)d_in[4];
    const float* W1        = (const float*)d_in[5];
    const float* b1        = (const float*)d_in[6];
    const float* W2        = (const float*)d_in[7];
    const float* b2        = (const float*)d_in[8];
    const float* Wout      = (const float*)d_in[9];
    const float* bout      = (const float*)d_in[10];
    const int*   ci        = (const int*)d_in[11];
    const int*   mi        = (const int*)d_in[12];
    float* out = (float*)d_out;

    const int GB_T  = (NT + 255) / 256;
    const int GB_C  = (NC + 255) / 256;
    const int GB_M  = (NM + 255) / 256;
    const int GB_E  = ((NC + NM) * 4 + 255) / 256;
    const int GB0_T = (NT + 127) / 128;   // 7813
    const int GB0_C = (NC + 127) / 128;   // 3907
    const int GB0_M = (NM + 127) / 128;   // 782

    static bool attr_set = false;
    if (!attr_set) {
        cudaFuncSetAttribute(ka0_mma, cudaFuncAttributeMaxDynamicSharedMemorySize, KA0_SMEM);
        attr_set = true;
    }

    zero_kernel<<<4096, 256>>>();
    count_kernel<<<GB_T, 256>>>(ci, mi);

    // Layer 0 (K=128): TF32 MMA path. W0 [5,128,16] -> etype stride 2048
    kb0_mma<<<GB0_C, 256>>>(NC, emb_card,  W0,        b0,      0);
    kb0_mma<<<GB0_M, 256>>>(NM, emb_merch, W0 + 2048, b0 + 16, 1);
    ka0_mma<<<GB0_T, 256, KA0_SMEM>>>(feats, W0 + 4096, b0 + 32, ci, mi);
    ke_kernel<<<GB_E, 256>>>();

    // Layer 1 (K=16): FFMA path. W1 [5,16,16] -> etype stride 256
    kb_kernel<16, true><<<GB_C, 256>>>(NC, nullptr, 1, W1,       b1,      0);
    kb_kernel<16, true><<<GB_M, 256>>>(NM, nullptr, 2, W1 + 256, b1 + 16, 1);
    ka_kernel<16, true><<<GB_T, 256>>>(nullptr, 1, W1 + 512, b1 + 32, ci, mi);
    ke_kernel<<<GB_E, 256>>>();

    // Layer 2: only bufc/bufm + self projection, fused with output head
    kb_kernel<16, true><<<GB_C, 256>>>(NC, nullptr, 1, W2,       b2,      0);
    kb_kernel<16, true><<<GB_M, 256>>>(NM, nullptr, 2, W2 + 256, b2 + 16, 1);
    ka_out_kernel<<<GB_T, 256>>>(W2 + 512, b2 + 32, ci, mi, Wout, bout, out);
}

// round 4
// speedup vs baseline: 1.4254x; 1.0741x over previous
#include <cuda_runtime.h>
#include <cstdint>

#define NT 1000000
#define NC 500000
#define NM 100000

// ---------------- scratch (static device globals; no allocation) ----------------
__device__ float g_ht[NT * 16];       // txn self-projection (gather deferred to consumer)
__device__ float g_hc[NC * 16];
__device__ float g_hm[NM * 16];
__device__ float g_bufcA[NC * 16];    // card proj, layers 0 and 2
__device__ float g_bufmA[NM * 16];
__device__ float g_bufcB[NC * 16];    // card proj, layer 1
__device__ float g_bufmB[NM * 16];
__device__ float g_sumc[NC * 16];
__device__ float g_summ[NM * 16];
__device__ float g_cntc[NC];
__device__ float g_cntm[NM];

#define GC_BLK 1954   // ceil(NC/256)
#define GM_BLK 391    // ceil(NM/256)
#define GT_BLK 3907   // ceil(NT/256)

__device__ __forceinline__ float lrelu_f(float v) { return v > 0.f ? v : 0.01f * v; }

__device__ __forceinline__ void red4(float* p, float a, float b, float c, float d) {
    asm volatile("red.global.add.v4.f32 [%0], {%1,%2,%3,%4};"
                 :: "l"(p), "f"(a), "f"(b), "f"(c), "f"(d) : "memory");
}

__device__ __forceinline__ uint32_t f2tf32(float f) {
    uint32_t r; asm("cvt.rna.tf32.f32 %0, %1;" : "=r"(r) : "f"(f)); return r;
}

__device__ __forceinline__ void mma_tf32(float& d0, float& d1, float& d2, float& d3,
                                         uint32_t a0, uint32_t a1, uint32_t a2, uint32_t a3,
                                         uint32_t b0, uint32_t b1) {
    asm volatile("mma.sync.aligned.m16n8k8.row.col.f32.tf32.tf32.f32 "
                 "{%0,%1,%2,%3}, {%4,%5,%6,%7}, {%8,%9}, {%0,%1,%2,%3};"
                 : "+f"(d0), "+f"(d1), "+f"(d2), "+f"(d3)
                 : "r"(a0), "r"(a1), "r"(a2), "r"(a3), "r"(b0), "r"(b1));
}

__device__ __forceinline__ void cp_async16(void* dst_smem, const void* src, bool pred) {
    uint32_t d = (uint32_t)__cvta_generic_to_shared(dst_smem);
    asm volatile("cp.async.cg.shared.global [%0], [%1], 16, %2;"
                 :: "r"(d), "l"(src), "r"(pred ? 16 : 0));
}
#define CP_COMMIT() asm volatile("cp.async.commit_group;")
#define CP_WAIT1()  asm volatile("cp.async.wait_group 1;")

// ---------------- zero sums + counts ----------------
__global__ void zero_kernel() {
    const int n1 = NC * 16;
    const int n2 = n1 + NM * 16;
    const int n3 = n2 + NC;
    const int n4 = n3 + NM;
    for (int i = blockIdx.x * blockDim.x + threadIdx.x; i < n4; i += gridDim.x * blockDim.x) {
        if (i < n1)      g_sumc[i] = 0.f;
        else if (i < n2) g_summ[i - n1] = 0.f;
        else if (i < n3) g_cntc[i - n2] = 0.f;
        else             g_cntm[i - n3] = 0.f;
    }
}

__global__ void count_kernel(const int* __restrict__ ci, const int* __restrict__ mi) {
    int i = blockIdx.x * blockDim.x + threadIdx.x;
    if (i < NT) {
        atomicAdd(&g_cntc[ci[i]], 1.f);
        atomicAdd(&g_cntm[mi[i]], 1.f);
    }
}

// ================= TF32 MMA mainloop, 256-row block, K=128 =================
// smem layout (dynamic, 92416 bytes):
//   [0, 61440)       float Xs[3][256][20]    (reused as Cs[256][52] post-loop)
//   [61440, 90112)   uint32_t Ws[128][56]
//   [90112, 90304)   float bs[48]
//   [90368, 91392)   int ciS[256]
//   [91392, 92416)   int miS[256]
#define M0_SMEM 92416

template <int NTILES>
__device__ __forceinline__ void mma_loop_256(const float* __restrict__ X, int nrows, int row0,
                                             const float* __restrict__ Wg,
                                             char* smem, float c[2][NTILES][4]) {
    float(*Xs)[20] = (float(*)[20])smem;
    uint32_t(*Ws)[56] = (uint32_t(*)[56])(smem + 61440);
    const int tid = threadIdx.x;
    const int lane = tid & 31, wid = tid >> 5;
    const int gid = lane >> 2, tig = lane & 3;

    for (int i = tid; i < 128 * NTILES * 8; i += 256) {
        int k = i / (NTILES * 8), cc = i % (NTILES * 8);
        Ws[k][cc] = f2tf32(Wg[(cc >> 4) * 2048 + k * 16 + (cc & 15)]);
    }

#pragma unroll
    for (int mt = 0; mt < 2; mt++)
#pragma unroll
        for (int nt = 0; nt < NTILES; nt++)
#pragma unroll
            for (int q = 0; q < 4; q++) c[mt][nt][q] = 0.f;

    auto prefetch = [&](int ch) {
        int st = ch % 3;
#pragma unroll
        for (int j = 0; j < 4; j++) {
            int idx = tid + j * 256;
            int r = idx >> 2, p = idx & 3;
            int row = row0 + r;
            bool ok = row < nrows;
            const float* src = X + (size_t)(ok ? row : 0) * 128 + ch * 16 + p * 4;
            cp_async16(&Xs[st * 256 + r][p * 4], src, ok);
        }
    };
    prefetch(0); CP_COMMIT();
    prefetch(1); CP_COMMIT();

    for (int ch = 0; ch < 8; ch++) {
        CP_WAIT1();
        __syncthreads();
        if (ch + 2 < 8) prefetch(ch + 2);
        CP_COMMIT();
        const float(*xb)[20] = Xs + (ch % 3) * 256;
#pragma unroll
        for (int ks = 0; ks < 2; ks++) {
            int k0 = ks * 8, kk = ch * 16 + k0;
#pragma unroll
            for (int mt = 0; mt < 2; mt++) {
                int rb = wid * 32 + mt * 16;
                uint32_t a0 = f2tf32(xb[rb + gid][k0 + tig]);
                uint32_t a1 = f2tf32(xb[rb + 8 + gid][k0 + tig]);
                uint32_t a2 = f2tf32(xb[rb + gid][k0 + tig + 4]);
                uint32_t a3 = f2tf32(xb[rb + 8 + gid][k0 + tig + 4]);
#pragma unroll
                for (int nt = 0; nt < NTILES; nt++) {
                    uint32_t b0 = Ws[kk + tig][nt * 8 + gid];
                    uint32_t b1 = Ws[kk + tig + 4][nt * 8 + gid];
                    mma_tf32(c[mt][nt][0], c[mt][nt][1], c[mt][nt][2], c[mt][nt][3],
                             a0, a1, a2, a3, b0, b1);
                }
            }
        }
    }
}

// ================= mega0: all three layer-0 projections in ONE launch =================
__global__ __launch_bounds__(256, 2) void mega0(const float* __restrict__ feats,
                                                const float* __restrict__ emb_card,
                                                const float* __restrict__ emb_merch,
                                                const float* __restrict__ W0,
                                                const float* __restrict__ b0,
                                                const int* __restrict__ ci,
                                                const int* __restrict__ mi) {
    extern __shared__ __align__(16) char smem[];
    float* bs = (float*)(smem + 90112);
    int* ciS = (int*)(smem + 90368);
    int* miS = (int*)(smem + 91392);
    const int tid = threadIdx.x, lane = tid & 31, wid = tid >> 5;
    const int gid = lane >> 2, tig = lane & 3;
    int b = blockIdx.x;

    if (b < GC_BLK + GM_BLK) {
        // ---- node projection role (card / merchant) ----
        bool isM = b >= GC_BLK;
        int row0 = (isM ? (b - GC_BLK) : b) * 256;
        int nrows = isM ? NM : NC;
        const float* X = isM ? emb_merch : emb_card;
        const float* Wg = W0 + (isM ? 2048 : 0);
        const float* B = b0 + (isM ? 16 : 0);
        float* out = isM ? g_bufmA : g_bufcA;
        if (tid < 16) bs[tid] = B[tid];
        float c[2][2][4];
        mma_loop_256<2>(X, nrows, row0, Wg, smem, c);
#pragma unroll
        for (int mt = 0; mt < 2; mt++)
#pragma unroll
            for (int nt = 0; nt < 2; nt++) {
                int col = nt * 8 + 2 * tig;
                int r0_ = row0 + wid * 32 + mt * 16 + gid, r1_ = r0_ + 8;
                float bx = bs[col], by = bs[col + 1];
                if (r0_ < nrows)
                    *(float2*)(out + (size_t)r0_ * 16 + col) =
                        make_float2(c[mt][nt][0] + bx, c[mt][nt][1] + by);
                if (r1_ < nrows)
                    *(float2*)(out + (size_t)r1_ * 16 + col) =
                        make_float2(c[mt][nt][2] + bx, c[mt][nt][3] + by);
            }
    } else {
        // ---- txn role: feats @ W0[2..4]; self -> g_ht, scatter -> sums ----
        int row0 = (b - GC_BLK - GM_BLK) * 256;
        if (tid < 48) bs[tid] = b0[32 + tid];
        {
            int row = row0 + tid;
            ciS[tid] = (row < NT) ? ci[row] : 0;
            miS[tid] = (row < NT) ? mi[row] : 0;
        }
        float c[2][6][4];
        mma_loop_256<6>(feats, NT, row0, W0 + 4096, smem, c);

        __syncthreads();                      // Xs dead; reuse as Cs[256][52]
        float* Cs = (float*)smem;
#pragma unroll
        for (int mt = 0; mt < 2; mt++)
#pragma unroll
            for (int nt = 0; nt < 6; nt++) {
                int ra = wid * 32 + mt * 16 + gid, rb = ra + 8, col = nt * 8 + 2 * tig;
                *(float2*)(Cs + ra * 52 + col) = make_float2(c[mt][nt][0], c[mt][nt][1]);
                *(float2*)(Cs + rb * 52 + col) = make_float2(c[mt][nt][2], c[mt][nt][3]);
            }
        __syncthreads();

        const int cg = tid & 3, rg = tid >> 2;
#pragma unroll
        for (int pass = 0; pass < 4; pass++) {
            int r = pass * 64 + rg, row = row0 + r;
            if (row < NT) {
                int cI = ciS[r], mI = miS[r];
#pragma unroll
                for (int u = 0; u < 3; u++) {
                    int q = cg * 12 + u * 4;
                    float4 v = *(const float4*)(Cs + r * 52 + q);
                    float vx = v.x + bs[q + 0], vy = v.y + bs[q + 1];
                    float vz = v.z + bs[q + 2], vw = v.w + bs[q + 3];
                    int e = q >> 4, j = q & 15;
                    if (e == 0)
                        *(float4*)(g_ht + (size_t)row * 16 + j) = make_float4(vx, vy, vz, vw);
                    else if (e == 1)
                        red4(&g_sumc[(size_t)cI * 16 + j], vx, vy, vz, vw);
                    else
                        red4(&g_summ[(size_t)mI * 16 + j], vx, vy, vz, vw);
                }
            }
        }
    }
}

// ---------------- segment mean finalize (+ re-zero sums for next layer) ----------------
__global__ void ke_kernel() {
    int i = blockIdx.x * blockDim.x + threadIdx.x;
    const int q1 = NC * 4;
    const int qt = q1 + NM * 4;
    if (i >= qt) return;
    const float4 z = make_float4(0.f, 0.f, 0.f, 0.f);
    if (i < q1) {
        float inv = 1.f / fmaxf(g_cntc[i >> 2], 1.f);
        float4 v = ((float4*)g_sumc)[i];
        ((float4*)g_hc)[i] = make_float4(v.x * inv, v.y * inv, v.z * inv, v.w * inv);
        ((float4*)g_sumc)[i] = z;
    } else {
        int j = i - q1;
        float inv = 1.f / fmaxf(g_cntm[j >> 2], 1.f);
        float4 v = ((float4*)g_summ)[j];
        ((float4*)g_hm)[j] = make_float4(v.x * inv, v.y * inv, v.z * inv, v.w * inv);
        ((float4*)g_summ)[j] = z;
    }
}

// ================= mega1: all three layer-1 projections (K=16, FFMA) =================
__global__ __launch_bounds__(256) void mega1(const float* __restrict__ W1,
                                             const float* __restrict__ b1,
                                             const int* __restrict__ ci,
                                             const int* __restrict__ mi) {
    __shared__ float Xs[256 * 20];
    __shared__ float Ws[16 * 48];
    __shared__ float bs[48];
    __shared__ int ciS[256], miS[256];
    const int tid = threadIdx.x;
    int b = blockIdx.x;

    if (b < GC_BLK + GM_BLK) {
        // ---- node role: lrelu(h) @ W1[0|1] + b -> bufB ----
        bool isM = b >= GC_BLK;
        int row0 = (isM ? (b - GC_BLK) : b) * 256;
        int nrows = isM ? NM : NC;
        const float* X = isM ? g_hm : g_hc;
        const float* W = W1 + (isM ? 256 : 0);
        const float* B = b1 + (isM ? 16 : 0);
        float* out = isM ? g_bufmB : g_bufcB;

        if (tid < 256) Ws[tid] = W[tid];
        if (tid < 16) bs[tid] = B[tid];
#pragma unroll
        for (int i = 0; i < 4; i++) {
            int idx = tid + i * 256;
            int r = idx >> 2, p = idx & 3;
            int row = row0 + r;
            float4 v = make_float4(0.f, 0.f, 0.f, 0.f);
            if (row < nrows) v = *(const float4*)(X + (size_t)row * 16 + p * 4);
            v.x = lrelu_f(v.x); v.y = lrelu_f(v.y); v.z = lrelu_f(v.z); v.w = lrelu_f(v.w);
            *(float4*)(Xs + r * 20 + p * 4) = v;
        }
        __syncthreads();

        const int cg = tid & 1, rg = tid >> 1;
        float acc[2][8];
#pragma unroll
        for (int a = 0; a < 2; a++)
#pragma unroll
            for (int q = 0; q < 8; q++) acc[a][q] = 0.f;
#pragma unroll
        for (int kk = 0; kk < 16; kk++) {
            const float* wr = &Ws[kk * 16 + cg * 8];
            float4 w0 = *(const float4*)(wr);
            float4 w1 = *(const float4*)(wr + 4);
            float wv[8] = {w0.x, w0.y, w0.z, w0.w, w1.x, w1.y, w1.z, w1.w};
#pragma unroll
            for (int rr = 0; rr < 2; rr++) {
                float x = Xs[(rg + rr * 128) * 20 + kk];
#pragma unroll
                for (int cc = 0; cc < 8; cc++) acc[rr][cc] += x * wv[cc];
            }
        }
#pragma unroll
        for (int rr = 0; rr < 2; rr++) {
            int row = row0 + rg + rr * 128;
            if (row < nrows) {
                *(float4*)(out + (size_t)row * 16 + cg * 8) =
                    make_float4(acc[rr][0] + bs[cg * 8 + 0], acc[rr][1] + bs[cg * 8 + 1],
                                acc[rr][2] + bs[cg * 8 + 2], acc[rr][3] + bs[cg * 8 + 3]);
                *(float4*)(out + (size_t)row * 16 + cg * 8 + 4) =
                    make_float4(acc[rr][4] + bs[cg * 8 + 4], acc[rr][5] + bs[cg * 8 + 5],
                                acc[rr][6] + bs[cg * 8 + 6], acc[rr][7] + bs[cg * 8 + 7]);
            }
        }
    } else {
        // ---- txn role: x_t = lrelu(ht + bufcA[ci] + bufmA[mi]); proj W1[2..4] ----
        int row0 = (b - GC_BLK - GM_BLK) * 256;
        for (int i = tid; i < 16 * 48; i += 256) {
            int k = i / 48, c = i % 48;
            Ws[i] = W1[512 + (c >> 4) * 256 + k * 16 + (c & 15)];
        }
        if (tid < 48) bs[tid] = b1[32 + tid];
        {
            int row = row0 + tid;
            ciS[tid] = (row < NT) ? ci[row] : 0;
            miS[tid] = (row < NT) ? mi[row] : 0;
        }
        __syncthreads();

        const float4* ht4 = (const float4*)g_ht;
        const float4* bc4 = (const float4*)g_bufcA;
        const float4* bm4 = (const float4*)g_bufmA;
#pragma unroll
        for (int i = 0; i < 4; i++) {
            int idx = tid + i * 256;
            int r = idx >> 2, p = idx & 3;
            int row = row0 + r;
            float4 v = make_float4(0.f, 0.f, 0.f, 0.f);
            if (row < NT) {
                float4 a = ht4[(size_t)row * 4 + p];
                float4 gc = bc4[(size_t)ciS[r] * 4 + p];
                float4 gm = bm4[(size_t)miS[r] * 4 + p];
                v.x = lrelu_f(a.x + gc.x + gm.x);
                v.y = lrelu_f(a.y + gc.y + gm.y);
                v.z = lrelu_f(a.z + gc.z + gm.z);
                v.w = lrelu_f(a.w + gc.w + gm.w);
            }
            *(float4*)(Xs + r * 20 + p * 4) = v;
        }
        __syncthreads();

        const int cg = tid & 3, rg = tid >> 2;
        float acc[4][12];
#pragma unroll
        for (int a = 0; a < 4; a++)
#pragma unroll
            for (int q = 0; q < 12; q++) acc[a][q] = 0.f;
#pragma unroll
        for (int kk = 0; kk < 16; kk++) {
            const float* wr = &Ws[kk * 48 + cg * 12];
            float4 w0 = *(const float4*)(wr);
            float4 w1 = *(const float4*)(wr + 4);
            float4 w2 = *(const float4*)(wr + 8);
            float wv[12] = {w0.x, w0.y, w0.z, w0.w, w1.x, w1.y, w1.z, w1.w,
                            w2.x, w2.y, w2.z, w2.w};
#pragma unroll
            for (int rr = 0; rr < 4; rr++) {
                float x = Xs[(rg + rr * 64) * 20 + kk];
#pragma unroll
                for (int cc = 0; cc < 12; cc++) acc[rr][cc] += x * wv[cc];
            }
        }

#pragma unroll
        for (int rr = 0; rr < 4; rr++) {
            int r = rg + rr * 64;
            int row = row0 + r;
            if (row < NT) {
                int cI = ciS[r], mI = miS[r];
#pragma unroll
                for (int u = 0; u < 3; u++) {
                    int q = cg * 12 + u * 4;
                    float vx = acc[rr][u * 4 + 0] + bs[q + 0];
                    float vy = acc[rr][u * 4 + 1] + bs[q + 1];
                    float vz = acc[rr][u * 4 + 2] + bs[q + 2];
                    float vw = acc[rr][u * 4 + 3] + bs[q + 3];
                    int e = q >> 4, j = q & 15;
                    if (e == 0)
                        *(float4*)(g_ht + (size_t)row * 16 + j) = make_float4(vx, vy, vz, vw);
                    else if (e == 1)
                        red4(&g_sumc[(size_t)cI * 16 + j], vx, vy, vz, vw);
                    else
                        red4(&g_summ[(size_t)mI * 16 + j], vx, vy, vz, vw);
                }
            }
        }
    }
}

// ================= mega2: layer-2 card/merch projections only =================
__global__ __launch_bounds__(256) void mega2(const float* __restrict__ W2,
                                             const float* __restrict__ b2) {
    __shared__ float Xs[256 * 20];
    __shared__ float Ws[16 * 16];
    __shared__ float bs[16];
    const int tid = threadIdx.x;
    int b = blockIdx.x;
    bool isM = b >= GC_BLK;
    int row0 = (isM ? (b - GC_BLK) : b) * 256;
    int nrows = isM ? NM : NC;
    const float* X = isM ? g_hm : g_hc;
    const float* W = W2 + (isM ? 256 : 0);
    const float* B = b2 + (isM ? 16 : 0);
    float* out = isM ? g_bufmA : g_bufcA;

    if (tid < 256) Ws[tid] = W[tid];
    if (tid < 16) bs[tid] = B[tid];
#pragma unroll
    for (int i = 0; i < 4; i++) {
        int idx = tid + i * 256;
        int r = idx >> 2, p = idx & 3;
        int row = row0 + r;
        float4 v = make_float4(0.f, 0.f, 0.f, 0.f);
        if (row < nrows) v = *(const float4*)(X + (size_t)row * 16 + p * 4);
        v.x = lrelu_f(v.x); v.y = lrelu_f(v.y); v.z = lrelu_f(v.z); v.w = lrelu_f(v.w);
        *(float4*)(Xs + r * 20 + p * 4) = v;
    }
    __syncthreads();

    const int cg = tid & 1, rg = tid >> 1;
    float acc[2][8];
#pragma unroll
    for (int a = 0; a < 2; a++)
#pragma unroll
        for (int q = 0; q < 8; q++) acc[a][q] = 0.f;
#pragma unroll
    for (int kk = 0; kk < 16; kk++) {
        const float* wr = &Ws[kk * 16 + cg * 8];
        float4 w0 = *(const float4*)(wr);
        float4 w1 = *(const float4*)(wr + 4);
        float wv[8] = {w0.x, w0.y, w0.z, w0.w, w1.x, w1.y, w1.z, w1.w};
#pragma unroll
        for (int rr = 0; rr < 2; rr++) {
            float x = Xs[(rg + rr * 128) * 20 + kk];
#pragma unroll
            for (int cc = 0; cc < 8; cc++) acc[rr][cc] += x * wv[cc];
        }
    }
#pragma unroll
    for (int rr = 0; rr < 2; rr++) {
        int row = row0 + rg + rr * 128;
        if (row < nrows) {
            *(float4*)(out + (size_t)row * 16 + cg * 8) =
                make_float4(acc[rr][0] + bs[cg * 8 + 0], acc[rr][1] + bs[cg * 8 + 1],
                            acc[rr][2] + bs[cg * 8 + 2], acc[rr][3] + bs[cg * 8 + 3]);
            *(float4*)(out + (size_t)row * 16 + cg * 8 + 4) =
                make_float4(acc[rr][4] + bs[cg * 8 + 4], acc[rr][5] + bs[cg * 8 + 5],
                            acc[rr][6] + bs[cg * 8 + 6], acc[rr][7] + bs[cg * 8 + 7]);
        }
    }
}

// ================= final: x_t gather (B bufs) + self proj + head gather (A bufs) =================
__global__ __launch_bounds__(256) void ka_out_kernel(const float* __restrict__ W,
                                                     const float* __restrict__ B,
                                                     const int* __restrict__ ci,
                                                     const int* __restrict__ mi,
                                                     const float* __restrict__ Wout,
                                                     const float* __restrict__ Bout,
                                                     float* __restrict__ out) {
    __shared__ float Xs[256 * 20];
    __shared__ float Ws[16 * 16];
    __shared__ float bs[16];
    __shared__ float wo[32];
    __shared__ int ciS[256];
    __shared__ int miS[256];

    const int tid = threadIdx.x;
    const int cg = tid & 1;
    const int rg = tid >> 1;
    const int row0 = blockIdx.x * 256;

    if (tid < 256) Ws[tid] = W[tid];
    if (tid < 16) bs[tid] = B[tid];
    if (tid < 32) wo[tid] = Wout[tid];
    {
        int row = row0 + tid;
        ciS[tid] = (row < NT) ? ci[row] : 0;
        miS[tid] = (row < NT) ? mi[row] : 0;
    }
    __syncthreads();

    const float4* ht4 = (const float4*)g_ht;
    const float4* bcB = (const float4*)g_bufcB;
    const float4* bmB = (const float4*)g_bufmB;
#pragma unroll
    for (int i = 0; i < 4; i++) {
        int idx = tid + i * 256;
        int r = idx >> 2, p = idx & 3;
        int row = row0 + r;
        float4 v = make_float4(0.f, 0.f, 0.f, 0.f);
        if (row < NT) {
            float4 a = ht4[(size_t)row * 4 + p];
            float4 gc = bcB[(size_t)ciS[r] * 4 + p];
            float4 gm = bmB[(size_t)miS[r] * 4 + p];
            v.x = lrelu_f(a.x + gc.x + gm.x);
            v.y = lrelu_f(a.y + gc.y + gm.y);
            v.z = lrelu_f(a.z + gc.z + gm.z);
            v.w = lrelu_f(a.w + gc.w + gm.w);
        }
        *(float4*)(Xs + r * 20 + p * 4) = v;
    }
    __syncthreads();

    float acc[2][8];
#pragma unroll
    for (int a = 0; a < 2; a++)
#pragma unroll
        for (int q = 0; q < 8; q++) acc[a][q] = 0.f;

#pragma unroll
    for (int kk = 0; kk < 16; kk++) {
        const float* wr = &Ws[kk * 16 + cg * 8];
        float4 w0 = *(const float4*)(wr);
        float4 w1 = *(const float4*)(wr + 4);
        float wv[8] = {w0.x, w0.y, w0.z, w0.w, w1.x, w1.y, w1.z, w1.w};
#pragma unroll
        for (int rr = 0; rr < 2; rr++) {
            float x = Xs[(rg + rr * 128) * 20 + kk];
#pragma unroll
            for (int cc = 0; cc < 8; cc++) acc[rr][cc] += x * wv[cc];
        }
    }

    const float4* bcA = (const float4*)g_bufcA;
    const float4* bmA = (const float4*)g_bufmA;
    float b0o = Bout[0], b1o = Bout[1];

#pragma unroll
    for (int rr = 0; rr < 2; rr++) {
        int r = rg + rr * 128;
        int row = row0 + r;
        int cI = ciS[r], mI = miS[r];
        float o0 = 0.f, o1 = 0.f;
#pragma unroll
        for (int u = 0; u < 2; u++) {
            int q = cg * 8 + u * 4;
            float4 gc = bcA[(size_t)cI * 4 + (q >> 2)];
            float4 gm = bmA[(size_t)mI * 4 + (q >> 2)];
            float vx = acc[rr][u * 4 + 0] + bs[q + 0] + gc.x + gm.x;
            float vy = acc[rr][u * 4 + 1] + bs[q + 1] + gc.y + gm.y;
            float vz = acc[rr][u * 4 + 2] + bs[q + 2] + gc.z + gm.z;
            float vw = acc[rr][u * 4 + 3] + bs[q + 3] + gc.w + gm.w;
            o0 += vx * wo[(q + 0) * 2 + 0] + vy * wo[(q + 1) * 2 + 0]
                + vz * wo[(q + 2) * 2 + 0] + vw * wo[(q + 3) * 2 + 0];
            o1 += vx * wo[(q + 0) * 2 + 1] + vy * wo[(q + 1) * 2 + 1]
                + vz * wo[(q + 2) * 2 + 1] + vw * wo[(q + 3) * 2 + 1];
        }
        o0 += __shfl_xor_sync(0xffffffffu, o0, 1);
        o1 += __shfl_xor_sync(0xffffffffu, o1, 1);
        if (cg == 0 && row < NT) {
            out[(size_t)row * 2 + 0] = o0 + b0o;
            out[(size_t)row * 2 + 1] = o1 + b1o;
        }
    }
}

// ---------------- launcher ----------------
extern "C" void kernel_launch(void* const* d_in, const int* in_sizes, int n_in,
                              void* d_out, int out_size) {
    (void)in_sizes; (void)n_in; (void)out_size;
    const float* feats     = (const float*)d_in[0];
    const float* emb_card  = (const float*)d_in[1];
    const float* emb_merch = (const float*)d_in[2];
    const float* W0        = (const float*)d_in[3];
    const float* b0        = (const float*)d_in[4];
    const float* W1        = (const float*)d_in[5];
    const float* b1        = (const float*)d_in[6];
    const float* W2        = (const float*)d_in[7];
    const float* b2        = (const float*)d_in[8];
    const float* Wout      = (const float*)d_in[9];
    const float* bout      = (const float*)d_in[10];
    const int*   ci        = (const int*)d_in[11];
    const int*   mi        = (const int*)d_in[12];
    float* out = (float*)d_out;

    const int GB_E = ((NC + NM) * 4 + 255) / 256;
    const int G_ALL = GC_BLK + GM_BLK + GT_BLK;   // 6252

    static bool attr_set = false;
    if (!attr_set) {
        cudaFuncSetAttribute(mega0, cudaFuncAttributeMaxDynamicSharedMemorySize, M0_SMEM);
        attr_set = true;
    }

    zero_kernel<<<4096, 256>>>();
    count_kernel<<<GT_BLK, 256>>>(ci, mi);

    mega0<<<G_ALL, 256, M0_SMEM>>>(feats, emb_card, emb_merch, W0, b0, ci, mi);
    ke_kernel<<<GB_E, 256>>>();

    mega1<<<G_ALL, 256>>>(W1, b1, ci, mi);
    ke_kernel<<<GB_E, 256>>>();

    mega2<<<GC_BLK + GM_BLK, 256>>>(W2, b2);
    ka_out_kernel<<<GT_BLK, 256>>>(W2 + 512, b2 + 32, ci, mi, Wout, bout, out);
}